// round 12
// baseline (speedup 1.0000x reference)
#include <cuda_runtime.h>
#include <math.h>

#define NI   128
#define ND   32
#define NH   4
#define NNEI 120
#define HC   (NH * NI)   // 512
#define LOCS_PER_CTA 14
#define THREADS 512
#define SLABF (NNEI * NI)   // 15360 floats, XOR-swizzled, stride 128

typedef unsigned long long u64t;

// ---------------- scratch (device globals) ----------------
__device__ float g_Mq[NI * HC];       // 128 x 512 : combined q/k projection (incl 1/sqrt(32))
__device__ float g_W2[HC * NI];       // 512 x 128 : combined v-projection @ Wh

// ---------------- K0: precompute Mq and W2 ----------------
__global__ void weights_prep_kernel(const float* __restrict__ Wq,
                                    const float* __restrict__ Wkv,
                                    const float* __restrict__ Wh)
{
    const int gid = blockIdx.x * blockDim.x + threadIdx.x;
    if (gid < NI * HC) {
        const int e = gid >> 9;
        const int hc = gid & 511;
        const int h = hc >> 7;
        const int c = hc & 127;
        float s = 0.f;
#pragma unroll
        for (int d = 0; d < ND; d++)
            s += Wq[e * 128 + d * 4 + h] * Wkv[c * 640 + d * 4 + h];
        g_Mq[gid] = s * 0.17677669529663687f;   // 1/sqrt(32)
    } else {
        const int g = gid - NI * HC;
        const int r = g >> 7;          // h*128 + c
        const int i = g & 127;
        const int h = r >> 7;
        const int c = r & 127;
        float s = 0.f;
#pragma unroll 8
        for (int ip = 0; ip < 128; ip++)
            s += Wkv[c * 640 + (32 + ip) * 4 + h] * Wh[(h * 128 + ip) * 128 + i];
        g_W2[g] = s;
    }
}

// ---------------- f32x2 packed helpers (ONLY qw projection + epilogue) ----------------
__device__ __forceinline__ u64t pk2(float x, float y)
{
    u64t r;
    asm("mov.b64 %0, {%1, %2};" : "=l"(r) : "f"(x), "f"(y));
    return r;
}
__device__ __forceinline__ void ffma2(u64t& d, u64t a, u64t b)
{
    asm("fma.rn.f32x2 %0, %1, %2, %0;" : "+l"(d) : "l"(a), "l"(b));
}
__device__ __forceinline__ void unpk2(u64t v, float& x, float& y)
{
    asm("mov.b64 {%0, %1}, %2;" : "=f"(x), "=f"(y) : "l"(v));
}

// ---------------- smem float layout (all 16B-aligned) ----------------
#define SO_SLAB0 0                         // 15360
#define SO_SLAB1 15360                     // 15360
#define SO_QW    30720                     // 7168 = 14*512  qw[il][h*128+c] (reused as epi partials)
#define SO_ACC   37888                     // 8192 = 512*16  accT[hc][l] stride 16 (g1p overlaid)
#define SO_PART  46080                     // 2048  (mask staging overlaid in prologue)
#define SO_WT    48128                     // 512   wt[j*4 + h]
#define SO_SW    48640                     // 1696
#define SO_MSK   50336                     // 1696 ints
#define SO_FLAG  52032                     // flags
#define SMEM_FLOATS (SO_FLAG + 8)
#define SMEM_BYTES  (SMEM_FLOATS * 4)      // ~208 KB -> 1 CTA/SM

__device__ __forceinline__ void cpa16(void* dst, const void* src)
{
    unsigned s = (unsigned)__cvta_generic_to_shared(dst);
    asm volatile("cp.async.cg.shared.global [%0], [%1], 16;\n" :: "r"(s), "l"(src));
}
__device__ __forceinline__ void cpa8(void* dst, const void* src)
{
    unsigned s = (unsigned)__cvta_generic_to_shared(dst);
    asm volatile("cp.async.ca.shared.global [%0], [%1], 8;\n" :: "r"(s), "l"(src));
}
__device__ __forceinline__ void cpa_commit()
{
    asm volatile("cp.async.commit_group;\n" ::: "memory");
}

__device__ __forceinline__ void stage_slab(float* dst, const float* gsrc, int tid)
{
#pragma unroll
    for (int w = 0; w < 8; w++) {
        const int idx = tid + w * THREADS;
        if (idx < SLABF / 4) {
            const int j = idx >> 5, q = idx & 31;
            cpa16(dst + j * NI + ((q ^ (j & 7)) << 2), gsrc + idx * 4);
        }
    }
    cpa_commit();
}

__global__ __launch_bounds__(THREADS, 1) void attn_core(
    const float* __restrict__ g1,
    const float* __restrict__ gg1,
    const void*  __restrict__ maskRaw,
    const float* __restrict__ sw,
    const float* __restrict__ bh,
    float* __restrict__ out,
    int nloctot)
{
    extern __shared__ float sm[];
    float* qw     = sm + SO_QW;             // qw per loc: [h*128 + c]
    float* accT   = sm + SO_ACC;
    float* g1p    = accT;                   // prologue overlay: g1p[e*16 + l]
    float* part   = sm + SO_PART;
    int*   mstage = (int*)part;             // prologue overlay
    float* wt     = sm + SO_WT;
    float* sws    = sm + SO_SW;
    int*   msks   = (int*)(sm + SO_MSK);
    int*   flags  = (int*)(sm + SO_FLAG);

    const int tid = threadIdx.x;
    const int locbase = blockIdx.x * LOCS_PER_CTA;
    const int count = min(LOCS_PER_CTA, nloctot - locbase);
    if (count <= 0) return;

    if (tid == 0) { flags[0] = 0; flags[1] = 0; }

    // prefetch slabs for loc0 and loc1
    stage_slab(sm + SO_SLAB0, gg1 + (size_t)locbase * SLABF, tid);
    stage_slab(sm + SO_SLAB1,
               gg1 + (size_t)(locbase + (count > 1 ? 1 : 0)) * SLABF, tid);

    // mask dtype detection from first 1KB (deterministic)
    if (tid < 64) {
        const uint4 v = ((const uint4*)maskRaw)[tid];
        const unsigned orw = v.x | v.y | v.z | v.w;
        if (orw & 0x00FFFF00u) atomicOr(&flags[0], 1);
        if (orw & 0xFF000000u) atomicOr(&flags[1], 1);
    }
    // g1 rows staged TRANSPOSED: g1p[e*16 + l]
    for (int idx = tid; idx < count * NI; idx += THREADS) {
        const int l = idx >> 7, e = idx & 127;
        g1p[e * 16 + l] = g1[(size_t)(locbase + l) * NI + e];
    }
    __syncthreads();   // B0

    const int f12 = flags[0], f3 = flags[1];
    const int nel = count * NNEI;

    // stage sw + raw mask via cp.async — overlaps qw projection
    {
        const float* swsrc = sw + (size_t)locbase * NNEI;
        for (int t2 = tid; t2 < (nel >> 2); t2 += THREADS)
            cpa16(sws + t2 * 4, swsrc + t2 * 4);
        if (f12) {
            const char* mb = (const char*)maskRaw + (size_t)locbase * NNEI;
            for (int t2 = tid; t2 < (nel >> 3); t2 += THREADS)
                cpa8((char*)mstage + t2 * 8, mb + t2 * 8);
        } else {
            const char* mb = (const char*)maskRaw + (size_t)locbase * NNEI * 4;
            for (int t2 = tid; t2 < (nel >> 2); t2 += THREADS)
                cpa16((char*)mstage + t2 * 16, mb + t2 * 16);
        }
        cpa_commit();
    }

    // qw projection (PACKED over l-pairs): few shared loads, 7 independent chains
    {
        u64t acc[7];
#pragma unroll
        for (int t = 0; t < 7; t++) acc[t] = 0ull;
        const float* mq = g_Mq + tid;
#pragma unroll 4
        for (int e = 0; e < NI; e++) {
            const float m = mq[e * HC];
            const u64t mm = pk2(m, m);
            const ulonglong2* gp = (const ulonglong2*)(g1p + e * 16);
            const ulonglong2 ga = gp[0];
            const ulonglong2 gb = gp[1];
            const ulonglong2 gc = gp[2];
            const u64t gd = *(const u64t*)(g1p + e * 16 + 12);
            ffma2(acc[0], ga.x, mm); ffma2(acc[1], ga.y, mm);
            ffma2(acc[2], gb.x, mm); ffma2(acc[3], gb.y, mm);
            ffma2(acc[4], gc.x, mm); ffma2(acc[5], gc.y, mm);
            ffma2(acc[6], gd,   mm);
        }
        __syncthreads();   // B1: g1p reads done (accT free)
        // store plain layout: qw[il][n] with n = tid = h*128+c
#pragma unroll
        for (int t = 0; t < 7; t++) {
            float x, y;
            unpk2(acc[t], x, y);
            qw[(2 * t + 0) * HC + tid] = x;
            qw[(2 * t + 1) * HC + tid] = y;
        }
    }

    // drain prologue staging, convert mask
    asm volatile("cp.async.wait_group 0;\n" ::: "memory");
    __syncthreads();       // B2
    {
#pragma unroll
        for (int w = 0; w < 4; w++) {
            const int t2 = tid + w * THREADS;
            if (t2 < nel) {
                int m;
                if (f12)      m = ((const unsigned char*)mstage)[t2] != 0;
                else if (f3)  m = ((const float*)mstage)[t2] != 0.f;
                else          m = mstage[t2] != 0;
                msks[t2] = m;
            }
        }
    }
    __syncthreads();       // B3

    // thread mappings
    const int wid = tid >> 5, lane = tid & 31;
    const int kq = wid & 3;
    const int jt = ((wid >> 2) << 5) + lane;
    const int cw = tid & 127;
    const int gw = tid >> 7;
    const int c4 = cw >> 2, co = cw & 3;

    // ---------------- per-location loop ----------------
    const float* qwl = qw;   // advanced by HC per iteration
    for (int il = 0; il < count; il++, qwl += HC) {
        asm volatile("cp.async.wait_group 1;\n" ::: "memory");
        __syncthreads();   // S1
        float* slab = sm + ((il & 1) ? SO_SLAB1 : SO_SLAB0);

        // --- logits: SCALAR, 4 independent accumulator chains (R7-proven) ---
        if (jt < NNEI) {
            const float* gr = slab + jt * NI + kq * 32;
            const int jm = jt & 7;
            const float4* q0 = (const float4*)(qwl + 0 * NI + kq * 32);
            const float4* q1 = (const float4*)(qwl + 1 * NI + kq * 32);
            const float4* q2 = (const float4*)(qwl + 2 * NI + kq * 32);
            const float4* q3 = (const float4*)(qwl + 3 * NI + kq * 32);
            float p0 = 0.f, p1 = 0.f, p2 = 0.f, p3 = 0.f;
#pragma unroll
            for (int i = 0; i < 8; i++) {
                const float4 g = *(const float4*)(gr + ((i ^ jm) << 2));
                const float4 a = q0[i]; p0 += g.x*a.x + g.y*a.y + g.z*a.z + g.w*a.w;
                const float4 b = q1[i]; p1 += g.x*b.x + g.y*b.y + g.z*b.z + g.w*b.w;
                const float4 c = q2[i]; p2 += g.x*c.x + g.y*c.y + g.z*c.z + g.w*c.w;
                const float4 d = q3[i]; p3 += g.x*d.x + g.y*d.y + g.z*d.z + g.w*d.w;
            }
            part[kq * HC + 0 * NI + jt] = p0;
            part[kq * HC + 1 * NI + jt] = p1;
            part[kq * HC + 2 * NI + jt] = p2;
            part[kq * HC + 3 * NI + jt] = p3;
        }
        __syncthreads();   // S2

        // --- masked softmax * sw (one warp per head) ---
        if (tid < 128) {
            const int h = tid >> 5, ln = tid & 31;
            float lv[4]; int mk[4];
            float mx = -INFINITY;
#pragma unroll
            for (int q = 0; q < 4; q++) {
                const int j = ln + q * 32;
                const int in = (j < NNEI) ? msks[il * NNEI + j] : 0;
                float L = -INFINITY;
                if (in) L = part[h * NI + j] + part[HC + h * NI + j]
                          + part[2 * HC + h * NI + j] + part[3 * HC + h * NI + j];
                lv[q] = L; mk[q] = in;
                mx = fmaxf(mx, L);
            }
#pragma unroll
            for (int off = 16; off > 0; off >>= 1)
                mx = fmaxf(mx, __shfl_xor_sync(0xFFFFFFFFu, mx, off));
            float ev[4];
            float sum = 0.f;
#pragma unroll
            for (int q = 0; q < 4; q++) {
                ev[q] = mk[q] ? __expf(lv[q] - mx) : 0.f;
                sum += ev[q];
            }
#pragma unroll
            for (int off = 16; off > 0; off >>= 1)
                sum += __shfl_xor_sync(0xFFFFFFFFu, sum, off);
            const float inv = (sum > 0.f) ? (1.f / sum) : 0.f;
#pragma unroll
            for (int q = 0; q < 4; q++) {
                const int j = ln + q * 32;
                if (j < NNEI)
                    wt[j * 4 + h] = mk[q] ? ev[q] * inv * sws[il * NNEI + j] : 0.f;
            }
        }
        __syncthreads();   // S3

        // --- weighted sum: SCALAR, 4 independent chains (R7-proven) ---
        {
            float s0 = 0.f, s1 = 0.f, s2 = 0.f, s3 = 0.f;
            const int j0 = gw * 30;
#pragma unroll
            for (int t = 0; t < 30; t++) {
                const int j = j0 + t;
                const float g = slab[j * NI + (((c4 ^ (j & 7)) << 2) | co)];
                const float4 w = *(const float4*)&wt[j * 4];
                s0 += w.x * g; s1 += w.y * g; s2 += w.z * g; s3 += w.w * g;
            }
            part[gw * HC + 0 * NI + cw] = s0;
            part[gw * HC + 1 * NI + cw] = s1;
            part[gw * HC + 2 * NI + cw] = s2;
            part[gw * HC + 3 * NI + cw] = s3;
        }
        __syncthreads();   // S4: slab free + partials visible

        if (il + 2 < count)
            stage_slab(sm + ((il & 1) ? SO_SLAB1 : SO_SLAB0),
                       gg1 + (size_t)(locbase + il + 2) * SLABF, tid);

        accT[(tid << 4) + il] = part[tid] + part[HC + tid]
                              + part[2 * HC + tid] + part[3 * HC + tid];
    }
    __syncthreads();

    // ---------------- fused output GEMM (PACKED over l-pairs): out[l][128] = a[l][512] @ W2 + bh ----------------
    {
        const int i = tid & 127, h2 = tid >> 7;
        u64t acc[7];
#pragma unroll
        for (int t = 0; t < 7; t++) acc[t] = 0ull;
        const float* w2p = g_W2 + (size_t)(h2 * NI) * NI + i;
#pragma unroll 4
        for (int k = 0; k < 128; k++) {
            const float w2 = w2p[k * NI];
            const u64t ww = pk2(w2, w2);
            const float* ap = accT + ((h2 * 128 + k) << 4);
            const ulonglong2* app = (const ulonglong2*)ap;
            const ulonglong2 v0 = app[0];
            const ulonglong2 v1 = app[1];
            const ulonglong2 v2 = app[2];
            const u64t v3 = *(const u64t*)(ap + 12);
            ffma2(acc[0], v0.x, ww); ffma2(acc[1], v0.y, ww);
            ffma2(acc[2], v1.x, ww); ffma2(acc[3], v1.y, ww);
            ffma2(acc[4], v2.x, ww); ffma2(acc[5], v2.y, ww);
            ffma2(acc[6], v3,   ww);
        }
        __syncthreads();
#pragma unroll
        for (int t = 0; t < 7; t++) {
            float x, y;
            unpk2(acc[t], x, y);
            qw[h2 * (LOCS_PER_CTA * NI) + (2 * t + 0) * NI + i] = x;
            qw[h2 * (LOCS_PER_CTA * NI) + (2 * t + 1) * NI + i] = y;
        }
    }
    __syncthreads();
    for (int o = tid; o < LOCS_PER_CTA * NI; o += THREADS) {
        const int l = o >> 7, ii = o & 127;
        if (l < count) {
            const float p0 = qw[o];
            const float p1 = qw[LOCS_PER_CTA * NI + o];
            const float p2 = qw[2 * LOCS_PER_CTA * NI + o];
            const float p3 = qw[3 * LOCS_PER_CTA * NI + o];
            out[(size_t)(locbase + l) * NI + ii] = (p0 + p1) + (p2 + p3) + bh[ii];
        }
    }
}

// ---------------- launch ----------------
extern "C" void kernel_launch(void* const* d_in, const int* in_sizes, int n_in,
                              void* d_out, int out_size)
{
    const float* g1   = (const float*)d_in[0];
    const float* gg1  = (const float*)d_in[1];
    const void*  mask = d_in[2];
    const float* sw   = (const float*)d_in[3];
    const float* Wq   = (const float*)d_in[4];
    const float* Wkv  = (const float*)d_in[5];
    const float* Wh   = (const float*)d_in[6];
    const float* bh   = (const float*)d_in[7];
    float* out = (float*)d_out;

    const int nloctot = in_sizes[0] / NI;   // 2048

    static int smem_cfg = 0;
    if (!smem_cfg) {
        cudaFuncSetAttribute(attn_core, cudaFuncAttributeMaxDynamicSharedMemorySize, SMEM_BYTES);
        smem_cfg = 1;
    }

    const int grid = (nloctot + LOCS_PER_CTA - 1) / LOCS_PER_CTA;   // 147

    weights_prep_kernel<<<512, 256>>>(Wq, Wkv, Wh);
    attn_core<<<grid, THREADS, SMEM_BYTES>>>(g1, gg1, mask, sw, bh, out, nloctot);
}

// round 14
// speedup vs baseline: 1.0476x; 1.0476x over previous
#include <cuda_runtime.h>
#include <math.h>

#define NI   128
#define ND   32
#define NH   4
#define NNEI 120
#define HC   (NH * NI)   // 512
#define BLOC 14
#define NTHR 512
#define SLABF (NNEI * NI)   // 15360 floats, XOR-swizzled, stride 128

// ---------------- scratch (device globals) ----------------
__device__ float g_Mq[NI * HC];       // 128 x 512 : combined q/k projection (incl 1/sqrt(32))
__device__ float g_W2[HC * NI];       // 512 x 128 : combined v-projection @ Wh

// ---------------- K0: precompute Mq and W2 ----------------
__global__ void weights_prep_kernel(const float* __restrict__ Wq,
                                    const float* __restrict__ Wkv,
                                    const float* __restrict__ Wh)
{
    const int gid = blockIdx.x * blockDim.x + threadIdx.x;
    if (gid < NI * HC) {
        const int e = gid >> 9;
        const int hc = gid & 511;
        const int h = hc >> 7;
        const int c = hc & 127;
        float s = 0.f;
#pragma unroll
        for (int d = 0; d < ND; d++)
            s += Wq[e * 128 + d * 4 + h] * Wkv[c * 640 + d * 4 + h];
        g_Mq[gid] = s * 0.17677669529663687f;   // 1/sqrt(32)
    } else {
        const int g = gid - NI * HC;
        const int r = g >> 7;          // h*128 + c
        const int i = g & 127;
        const int h = r >> 7;
        const int c = r & 127;
        float s = 0.f;
#pragma unroll 8
        for (int ip = 0; ip < 128; ip++)
            s += Wkv[c * 640 + (32 + ip) * 4 + h] * Wh[(h * 128 + ip) * 128 + i];
        g_W2[g] = s;
    }
}

// ---------------- smem float layout (all 16B-aligned) ----------------
#define SO_SLAB0 0                         // 15360
#define SO_SLAB1 15360                     // 15360
#define SO_QW    30720                     // 7168 = 14*512 qw[il][h*128+c] (epi partials reuse)
#define SO_ACC   37888                     // 8192 = 512*16 accT[hc][l] stride16 (g1s overlaid)
#define SO_PARTW 46080                     // 1024 = 2*512 wsum partials (2 row-groups)
#define SO_PARTL 47104                     // 2048 = 4*512 logits partials (mask staging overlaid)
#define SO_WT    49152                     // 512   wt[j*4 + h]
#define SO_SW    49664                     // 1696
#define SO_MSK   51360                     // 1696 ints
#define SO_FLAG  53056                     // flags
#define SMEM_FLOATS (SO_FLAG + 8)
#define SMEM_BYTES  (SMEM_FLOATS * 4)      // ~207 KB -> 1 CTA/SM

__device__ __forceinline__ void cpa16(void* dst, const void* src)
{
    unsigned s = (unsigned)__cvta_generic_to_shared(dst);
    asm volatile("cp.async.cg.shared.global [%0], [%1], 16;\n" :: "r"(s), "l"(src));
}
__device__ __forceinline__ void cpa8(void* dst, const void* src)
{
    unsigned s = (unsigned)__cvta_generic_to_shared(dst);
    asm volatile("cp.async.ca.shared.global [%0], [%1], 8;\n" :: "r"(s), "l"(src));
}
__device__ __forceinline__ void cpa_commit()
{
    asm volatile("cp.async.commit_group;\n" ::: "memory");
}

// all-thread slab stage (prologue only)
__device__ __forceinline__ void stage_slab_all(float* dst, const float* gsrc, int tid)
{
#pragma unroll
    for (int w = 0; w < 8; w++) {
        const int idx = tid + w * NTHR;
        if (idx < SLABF / 4) {
            const int j = idx >> 5, q = idx & 31;
            cpa16(dst + j * NI + ((q ^ (j & 7)) << 2), gsrc + idx * 4);
        }
    }
    cpa_commit();
}

// 256-thread slab stage (loop: issued by warps 8-15 only; t in [0,256))
__device__ __forceinline__ void stage_slab_256(float* dst, const float* gsrc, int t)
{
#pragma unroll
    for (int w = 0; w < 15; w++) {
        const int idx = t + w * 256;          // 15*256 == 3840 == SLABF/4 exactly
        const int j = idx >> 5, q = idx & 31;
        cpa16(dst + j * NI + ((q ^ (j & 7)) << 2), gsrc + idx * 4);
    }
    cpa_commit();
}

__global__ __launch_bounds__(NTHR, 1) void attn_pipe(
    const float* __restrict__ g1,
    const float* __restrict__ gg1,
    const void*  __restrict__ maskRaw,
    const float* __restrict__ sw,
    const float* __restrict__ bh,
    float* __restrict__ out,
    int nloctot)
{
    extern __shared__ float sm[];
    float* qw     = sm + SO_QW;
    float* accT   = sm + SO_ACC;
    float* g1s    = accT;                   // prologue overlay [0..1792)
    float* partW  = sm + SO_PARTW;          // [g*512 + h*128 + c], g in {0,1}
    float* partL  = sm + SO_PARTL;          // [kq*512 + h*128 + j]
    int*   mstage = (int*)partL;            // prologue overlay
    float* wt     = sm + SO_WT;
    float* sws    = sm + SO_SW;
    int*   msks   = (int*)(sm + SO_MSK);
    int*   flags  = (int*)(sm + SO_FLAG);

    const int tid = threadIdx.x;
    const int locbase = blockIdx.x * BLOC;
    const int count = min(BLOC, nloctot - locbase);
    if (count <= 0) return;

    if (tid == 0) { flags[0] = 0; flags[1] = 0; }

    // prefetch slabs for loc0 and loc1 (all threads)
    stage_slab_all(sm + SO_SLAB0, gg1 + (size_t)locbase * SLABF, tid);
    stage_slab_all(sm + SO_SLAB1,
                   gg1 + (size_t)(locbase + (count > 1 ? 1 : 0)) * SLABF, tid);

    // mask dtype detection from first 1KB (deterministic)
    if (tid < 64) {
        const uint4 v = ((const uint4*)maskRaw)[tid];
        const unsigned orw = v.x | v.y | v.z | v.w;
        if (orw & 0x00FFFF00u) atomicOr(&flags[0], 1);
        if (orw & 0xFF000000u) atomicOr(&flags[1], 1);
    }
    // g1 rows (overlaid on accT)
    if (tid < 32 * BLOC) {
        const int l = tid >> 5, e4 = tid & 31;
        if (l < count)
            *(float4*)&g1s[l * NI + e4 * 4] =
                *(const float4*)&g1[(size_t)(locbase + l) * NI + e4 * 4];
    }
    __syncthreads();   // B0

    const int f12 = flags[0], f3 = flags[1];
    const int nel = count * NNEI;

    // stage sw + raw mask via cp.async — overlaps qw projection
    {
        const float* swsrc = sw + (size_t)locbase * NNEI;
        for (int t2 = tid; t2 < (nel >> 2); t2 += NTHR)
            cpa16(sws + t2 * 4, swsrc + t2 * 4);
        if (f12) {
            const char* mb = (const char*)maskRaw + (size_t)locbase * NNEI;
            for (int t2 = tid; t2 < (nel >> 3); t2 += NTHR)
                cpa8((char*)mstage + t2 * 8, mb + t2 * 8);
        } else {
            const char* mb = (const char*)maskRaw + (size_t)locbase * NNEI * 4;
            for (int t2 = tid; t2 < (nel >> 2); t2 += NTHR)
                cpa16((char*)mstage + t2 * 16, mb + t2 * 16);
        }
        cpa_commit();
    }

    // qw projection (R7 scalar): qw[l][n] = g1[l,:] . Mq[:,n], n = tid
    {
        float acc[BLOC];
#pragma unroll
        for (int l = 0; l < BLOC; l++) acc[l] = 0.f;
        const float* mq = g_Mq + tid;
#pragma unroll 8
        for (int e = 0; e < NI; e++) {
            const float m = mq[e * HC];
#pragma unroll
            for (int l = 0; l < BLOC; l++)
                acc[l] += g1s[l * NI + e] * m;
        }
        __syncthreads();   // B1: g1s reads done (accT free)
#pragma unroll
        for (int l = 0; l < BLOC; l++) qw[l * HC + tid] = acc[l];
    }

    // drain all prologue groups; convert mask
    asm volatile("cp.async.wait_group 0;\n" ::: "memory");
    __syncthreads();       // B2
#pragma unroll
    for (int w = 0; w < 4; w++) {
        const int t2 = tid + w * NTHR;
        if (t2 < nel) {
            int m;
            if (f12)      m = ((const unsigned char*)mstage)[t2] != 0;
            else if (f3)  m = ((const float*)mstage)[t2] != 0.f;
            else          m = mstage[t2] != 0;
            msks[t2] = m;
        }
    }
    __syncthreads();       // B3: msks ready; partL (mstage) free

    const int wid = tid >> 5, lane = tid & 31;

    // ---- logits(0): full-width R7 mapping ----
    {
        const int kq = wid & 3;
        const int jt = ((wid >> 2) << 5) + lane;
        if (jt < NNEI) {
            const float* gr = sm + SO_SLAB0 + jt * NI + kq * 32;
            const int jm = jt & 7;
            const float4* q0 = (const float4*)(qw + 0 * NI + kq * 32);
            const float4* q1 = (const float4*)(qw + 1 * NI + kq * 32);
            const float4* q2 = (const float4*)(qw + 2 * NI + kq * 32);
            const float4* q3 = (const float4*)(qw + 3 * NI + kq * 32);
            float p0 = 0.f, p1 = 0.f, p2 = 0.f, p3 = 0.f;
#pragma unroll
            for (int i = 0; i < 8; i++) {
                const float4 g = *(const float4*)(gr + ((i ^ jm) << 2));
                const float4 a = q0[i]; p0 += g.x*a.x + g.y*a.y + g.z*a.z + g.w*a.w;
                const float4 b = q1[i]; p1 += g.x*b.x + g.y*b.y + g.z*b.z + g.w*b.w;
                const float4 c = q2[i]; p2 += g.x*c.x + g.y*c.y + g.z*c.z + g.w*c.w;
                const float4 d = q3[i]; p3 += g.x*d.x + g.y*d.y + g.z*d.z + g.w*d.w;
            }
            partL[kq * HC + 0 * NI + jt] = p0;
            partL[kq * HC + 1 * NI + jt] = p1;
            partL[kq * HC + 2 * NI + jt] = p2;
            partL[kq * HC + 3 * NI + jt] = p3;
        }
    }
    __syncthreads();   // B4

    // wsum mapping (warps 0-7): 256 threads, 2 row-groups x 60 rows
    const int cw = tid & 127;
    const int gh = (tid >> 7) & 1;
    const int c4 = cw >> 2, co = cw & 3;
    // logits mapping (warps 8-15): 256 threads, kq quarter + 2 j-rows
    const int tid2 = tid & 255;
    const int wid2 = tid2 >> 5;
    const int kq2 = wid2 & 3;
    const int jb = ((wid2 >> 2) << 5) + lane;   // [0,64)

    // ---------------- per-location pipelined loop ----------------
    for (int il = 0; il < count; il++) {
        // ---- Phase A: softmax(il) on warps 0-3 ; accT(il-1) on warps 4-15 ----
        if (tid < 128) {
            const int h = tid >> 5, ln = tid & 31;
            float lv[4]; int mk[4];
            float mx = -INFINITY;
#pragma unroll
            for (int q = 0; q < 4; q++) {
                const int j = ln + q * 32;
                const int in = (j < NNEI) ? msks[il * NNEI + j] : 0;
                float L = -INFINITY;
                if (in) L = partL[h * NI + j] + partL[HC + h * NI + j]
                          + partL[2 * HC + h * NI + j] + partL[3 * HC + h * NI + j];
                lv[q] = L; mk[q] = in;
                mx = fmaxf(mx, L);
            }
#pragma unroll
            for (int off = 16; off > 0; off >>= 1)
                mx = fmaxf(mx, __shfl_xor_sync(0xFFFFFFFFu, mx, off));
            float ev[4];
            float sum = 0.f;
#pragma unroll
            for (int q = 0; q < 4; q++) {
                ev[q] = mk[q] ? __expf(lv[q] - mx) : 0.f;
                sum += ev[q];
            }
#pragma unroll
            for (int off = 16; off > 0; off >>= 1)
                sum += __shfl_xor_sync(0xFFFFFFFFu, sum, off);
            const float inv = (sum > 0.f) ? (1.f / sum) : 0.f;
#pragma unroll
            for (int q = 0; q < 4; q++) {
                const int j = ln + q * 32;
                if (j < NNEI)
                    wt[j * 4 + h] = mk[q] ? ev[q] * inv * sws[il * NNEI + j] : 0.f;
            }
        } else if (il > 0) {
            for (int v = tid - 128; v < HC; v += 384)
                accT[(v << 4) + il - 1] = partW[v] + partW[HC + v];
        }
        __syncthreads();   // P1

        // ---- Phase B: wsum(il) on warps 0-7 ; wait+logits(il+1) on warps 8-15 ----
        if (tid < 256) {
            float* slab = sm + ((il & 1) ? SO_SLAB1 : SO_SLAB0);
            float s0 = 0.f, s1 = 0.f, s2 = 0.f, s3 = 0.f;
            const int j0 = gh * 60;
#pragma unroll 15
            for (int t = 0; t < 60; t++) {
                const int j = j0 + t;
                const float g = slab[j * NI + (((c4 ^ (j & 7)) << 2) | co)];
                const float4 w = *(const float4*)&wt[j * 4];
                s0 += w.x * g; s1 += w.y * g; s2 += w.z * g; s3 += w.w * g;
            }
            partW[gh * HC + 0 * NI + cw] = s0;
            partW[gh * HC + 1 * NI + cw] = s1;
            partW[gh * HC + 2 * NI + cw] = s2;
            partW[gh * HC + 3 * NI + cw] = s3;
        } else if (il + 1 < count) {
            // Drain OWN cp.async copies, then publish across warps 8-15 via a
            // named partial barrier: every issuer has waited before the barrier,
            // so after it ALL 256 threads' slab copies are visible. (This barrier
            // was missing in R13 -> raced on other threads' in-flight copies.)
            asm volatile("cp.async.wait_group 0;\n" ::: "memory");
            asm volatile("bar.sync 1, 256;" ::: "memory");
            const float* slab = sm + (((il + 1) & 1) ? SO_SLAB1 : SO_SLAB0);
            const float* qwl = qw + (il + 1) * HC;
            const int jA = jb;
            const int jB = jb + 64;
            const int doB = (jB < NNEI);
            const float* grA = slab + jA * NI + kq2 * 32;
            const float* grB = slab + jB * NI + kq2 * 32;
            const int jmA = jA & 7;
            const int jmB = jB & 7;
            const float4* q0 = (const float4*)(qwl + 0 * NI + kq2 * 32);
            const float4* q1 = (const float4*)(qwl + 1 * NI + kq2 * 32);
            const float4* q2 = (const float4*)(qwl + 2 * NI + kq2 * 32);
            const float4* q3 = (const float4*)(qwl + 3 * NI + kq2 * 32);
            float p0 = 0.f, p1 = 0.f, p2 = 0.f, p3 = 0.f;
            float r0 = 0.f, r1 = 0.f, r2 = 0.f, r3 = 0.f;
#pragma unroll
            for (int i = 0; i < 8; i++) {
                const float4 a = q0[i];
                const float4 b = q1[i];
                const float4 c = q2[i];
                const float4 d = q3[i];
                const float4 gA = *(const float4*)(grA + ((i ^ jmA) << 2));
                p0 += gA.x*a.x + gA.y*a.y + gA.z*a.z + gA.w*a.w;
                p1 += gA.x*b.x + gA.y*b.y + gA.z*b.z + gA.w*b.w;
                p2 += gA.x*c.x + gA.y*c.y + gA.z*c.z + gA.w*c.w;
                p3 += gA.x*d.x + gA.y*d.y + gA.z*d.z + gA.w*d.w;
                if (doB) {
                    const float4 gB = *(const float4*)(grB + ((i ^ jmB) << 2));
                    r0 += gB.x*a.x + gB.y*a.y + gB.z*a.z + gB.w*a.w;
                    r1 += gB.x*b.x + gB.y*b.y + gB.z*b.z + gB.w*b.w;
                    r2 += gB.x*c.x + gB.y*c.y + gB.z*c.z + gB.w*c.w;
                    r3 += gB.x*d.x + gB.y*d.y + gB.z*d.z + gB.w*d.w;
                }
            }
            partL[kq2 * HC + 0 * NI + jA] = p0;
            partL[kq2 * HC + 1 * NI + jA] = p1;
            partL[kq2 * HC + 2 * NI + jA] = p2;
            partL[kq2 * HC + 3 * NI + jA] = p3;
            if (doB) {
                partL[kq2 * HC + 0 * NI + jB] = r0;
                partL[kq2 * HC + 1 * NI + jB] = r1;
                partL[kq2 * HC + 2 * NI + jB] = r2;
                partL[kq2 * HC + 3 * NI + jB] = r3;
            }
        }
        __syncthreads();   // P2: slab il free; partW/partL visible

        // prefetch slab il+2 — issued ONLY by warps 8-15 (they also wait on it)
        if (il + 2 < count && tid >= 256)
            stage_slab_256(sm + ((il & 1) ? SO_SLAB1 : SO_SLAB0),
                           gg1 + (size_t)(locbase + il + 2) * SLABF, tid2);
    }

    // final accT row
    accT[(tid << 4) + (count - 1)] = partW[tid] + partW[HC + tid];
    __syncthreads();

    // ---------------- fused output GEMM (R7 scalar): out[l][128] = a[l][512] @ W2 + bh ----------------
    {
        const int i = tid & 127, h2 = tid >> 7;
        float acc[BLOC];
#pragma unroll
        for (int l = 0; l < BLOC; l++) acc[l] = 0.f;
        const float* w2p = g_W2 + (size_t)(h2 * NI) * NI + i;
#pragma unroll 4
        for (int k = 0; k < 128; k++) {
            const float w2 = w2p[k * NI];
            const float* ap = accT + ((h2 * 128 + k) << 4);
            const float4 v0 = *(const float4*)ap;
            const float4 v1 = *(const float4*)(ap + 4);
            const float4 v2 = *(const float4*)(ap + 8);
            const float2 v3 = *(const float2*)(ap + 12);
            acc[0]  += v0.x * w2; acc[1]  += v0.y * w2;
            acc[2]  += v0.z * w2; acc[3]  += v0.w * w2;
            acc[4]  += v1.x * w2; acc[5]  += v1.y * w2;
            acc[6]  += v1.z * w2; acc[7]  += v1.w * w2;
            acc[8]  += v2.x * w2; acc[9]  += v2.y * w2;
            acc[10] += v2.z * w2; acc[11] += v2.w * w2;
            acc[12] += v3.x * w2; acc[13] += v3.y * w2;
        }
        __syncthreads();
#pragma unroll
        for (int l = 0; l < BLOC; l++)
            qw[h2 * (BLOC * NI) + l * NI + i] = acc[l];   // reuse qw as partials
    }
    __syncthreads();
    for (int o = tid; o < BLOC * NI; o += NTHR) {
        const int l = o >> 7, ii = o & 127;
        if (l < count) {
            const float v = qw[o] + qw[BLOC * NI + o]
                          + qw[2 * BLOC * NI + o] + qw[3 * BLOC * NI + o] + bh[ii];
            out[(size_t)(locbase + l) * NI + ii] = v;
        }
    }
}

// ---------------- launch ----------------
extern "C" void kernel_launch(void* const* d_in, const int* in_sizes, int n_in,
                              void* d_out, int out_size)
{
    const float* g1   = (const float*)d_in[0];
    const float* gg1  = (const float*)d_in[1];
    const void*  mask = d_in[2];
    const float* sw   = (const float*)d_in[3];
    const float* Wq   = (const float*)d_in[4];
    const float* Wkv  = (const float*)d_in[5];
    const float* Wh   = (const float*)d_in[6];
    const float* bh   = (const float*)d_in[7];
    float* out = (float*)d_out;

    const int nloctot = in_sizes[0] / NI;   // 2048

    static int smem_cfg = 0;
    if (!smem_cfg) {
        cudaFuncSetAttribute(attn_pipe, cudaFuncAttributeMaxDynamicSharedMemorySize, SMEM_BYTES);
        smem_cfg = 1;
    }

    const int grid = (nloctot + BLOC - 1) / BLOC;   // 147

    weights_prep_kernel<<<512, 256>>>(Wq, Wkv, Wh);
    attn_pipe<<<grid, NTHR, SMEM_BYTES>>>(g1, gg1, mask, sw, bh, out, nloctot);
}